// round 4
// baseline (speedup 1.0000x reference)
#include <cuda_runtime.h>
#include <cuda_fp16.h>
#include <mma.h>
using namespace nvcuda;

#define TT 512
#define BB 64
#define HH 1024
#define G4 4096
#define BH (BB*HH)
#define OUT_SEQ ((size_t)TT*BB*HH)

// ---- gx (input-projection) GEMM params (R2 machinery) ----
#define KT2 64
#define NS2 4
#define AROW 72
#define STAGE_BYTES (2*64*AROW*2)
#define GX_SMEM (NS2*STAGE_BYTES)

// ---- persistent kernel params ----
#define NB 129                      // 43 blocks per stage x 3 stages
#define WPITCH 1032                 // halves; 2064B == 16 mod 128 -> conflict-free ldsm
#define WBYTES (96*WPITCH*2)        // 198144
#define ANS 3                       // A-tile triple buffer
#define ABYTES (ANS*64*AROW*2)      // 27648
#define PSMEM (WBYTES+ABYTES)       // 225792 <= 227KB
#define NITER 514

// ---------------- device scratch ----------------
__device__ __half g_Wc1h[(size_t)G4*1024];     // permuted W_ih layer0 (for gx)
__device__ __half g_Wcat[(size_t)3*G4*1024];   // [Whh1 | Wih2 | Whh2] permuted, half
__device__ float  g_b1[G4], g_b2[G4];
__device__ __half g_Xh[(size_t)TT*BB*1024];
__device__ float  g_GX1[(size_t)TT*BB*G4];     // x@Wih1^T + b1
__device__ __half g_h1p[2][BH];                // layer0 h ping-pong
__device__ __half g_h2p[2][BH];                // layer1 h ping-pong
__device__ __half g_H0h[2][BH];
__device__ float  g_gx2p[2][(size_t)BB*G4];    // h1@Wih2^T + b2 ping-pong
__device__ float  g_C1[BH], g_C2[BH];
__device__ unsigned g_cnt, g_phase;

__device__ __forceinline__ float sigmoidf_(float x){ return 1.f/(1.f+expf(-x)); }

__device__ __forceinline__ void cp16(void* dst, const void* src){
    unsigned s = (unsigned)__cvta_generic_to_shared(dst);
    asm volatile("cp.async.ca.shared.global [%0], [%1], 16;\n" :: "r"(s), "l"(src));
}

// ================= prep kernels =================
__global__ void prep_w(const float* __restrict__ Wih, const float* __restrict__ Whh,
                       const float* __restrict__ b){
    size_t i = (size_t)blockIdx.x*blockDim.x + threadIdx.x;
    if (i >= (size_t)G4*1024) return;
    int r = (int)(i >> 10), k = (int)(i & 1023);
    int u = r >> 2, g = r & 3;
    int src = (g << 10) | u;
    const size_t L1 = (size_t)G4*1024;
    g_Wc1h[(size_t)r*1024+k]           = __float2half(Wih[(size_t)src*1024+k]);
    g_Wcat[(size_t)r*1024+k]           = __float2half(Whh[(size_t)src*1024+k]);
    g_Wcat[(size_t)(G4+r)*1024+k]      = __float2half(Wih[L1+(size_t)src*1024+k]);
    g_Wcat[(size_t)(2*G4+r)*1024+k]    = __float2half(Whh[L1+(size_t)src*1024+k]);
    if (k == 0){ g_b1[r] = b[src]; g_b2[r] = b[G4+src]; }
}

__global__ void prep_x(const float* __restrict__ x){
    size_t i = (size_t)blockIdx.x*blockDim.x + threadIdx.x;
    size_t n4 = (size_t)TT*BB*1024/4;
    if (i >= n4) return;
    float4 v = ((const float4*)x)[i];
    __half2* dst = (__half2*)g_Xh;
    dst[2*i]   = __floats2half2_rn(v.x, v.y);
    dst[2*i+1] = __floats2half2_rn(v.z, v.w);
}

__global__ void init_c(const float* __restrict__ h0, const float* __restrict__ c0){
    int i = blockIdx.x*blockDim.x + threadIdx.x;
    if (i < BH){
        g_C1[i] = c0[i];
        g_C2[i] = c0[BH+i];
        g_H0h[0][i] = __float2half(h0[i]);
        g_H0h[1][i] = __float2half(h0[BH+i]);
    }
    if (i == 0){ g_cnt = 0; g_phase = 0; }
}

// ================= gx GEMM (from R2) =================
__device__ __forceinline__ void load_stage2(char* st, const __half* A, int lda,
        const __half* W, int ldw, int k0, int tid)
{
#pragma unroll
    for (int j = 0; j < 4; j++){
        int c = tid + j*256;
        int row = (c & 511) >> 3;
        int cc  = c & 7;
        if (c < 512)
            cp16(st + row*(AROW*2) + cc*16, A + (size_t)row*lda + k0 + cc*8);
        else
            cp16(st + 64*AROW*2 + row*(AROW*2) + cc*16, W + (size_t)row*ldw + k0 + cc*8);
    }
}

__global__ void gx_kernel(){
    extern __shared__ char smem[];
    int n0   = blockIdx.x * 64;
    int row0 = blockIdx.y * 64;
    int tid = threadIdx.x;
    int warp = tid >> 5;
    int wm = warp >> 1, wn = warp & 1;
    const __half* A = g_Xh + (size_t)row0*1024;
    const __half* W = g_Wc1h + (size_t)n0*1024;

    wmma::fragment<wmma::accumulator,16,16,16,float> acc[2];
    wmma::fill_fragment(acc[0], 0.f);
    wmma::fill_fragment(acc[1], 0.f);

#pragma unroll
    for (int p = 0; p < NS2-1; p++){
        load_stage2(smem + p*STAGE_BYTES, A, 1024, W, 1024, p*KT2, tid);
        asm volatile("cp.async.commit_group;\n");
    }
    for (int t = 0; t < 1024/KT2; t++){
        asm volatile("cp.async.wait_group 2;\n");
        __syncthreads();
        int pf = t + NS2 - 1;
        if (pf < 1024/KT2)
            load_stage2(smem + (pf & (NS2-1))*STAGE_BYTES, A, 1024, W, 1024, pf*KT2, tid);
        asm volatile("cp.async.commit_group;\n");

        const __half* As = (const __half*)(smem + (t & (NS2-1))*STAGE_BYTES);
        const __half* Ws = As + 64*AROW;
#pragma unroll
        for (int ks = 0; ks < KT2/16; ks++){
            wmma::fragment<wmma::matrix_a,16,16,16,__half,wmma::row_major> a;
            wmma::fragment<wmma::matrix_b,16,16,16,__half,wmma::col_major> b;
            wmma::load_matrix_sync(a, As + (wm*16)*AROW + ks*16, AROW);
            wmma::load_matrix_sync(b, Ws + (wn*32)*AROW + ks*16, AROW);
            wmma::mma_sync(acc[0], a, b, acc[0]);
            wmma::load_matrix_sync(b, Ws + (wn*32+16)*AROW + ks*16, AROW);
            wmma::mma_sync(acc[1], a, b, acc[1]);
        }
    }
    asm volatile("cp.async.wait_group 0;\n");
    __syncthreads();
    float* sm = (float*)smem;
    wmma::store_matrix_sync(sm + (wm*16)*64 + wn*32,      acc[0], 64, wmma::mem_row_major);
    wmma::store_matrix_sync(sm + (wm*16)*64 + wn*32 + 16, acc[1], 64, wmma::mem_row_major);
    __syncthreads();
#pragma unroll
    for (int i = 0; i < 16; i++){
        int e = tid + i*256;
        int row = e >> 6, col = e & 63;
        g_GX1[((size_t)row0 + row)*G4 + n0 + col] = sm[row*64+col] + g_b1[n0+col];
    }
}

// ================= persistent LSTM kernel =================
__device__ __forceinline__ void grid_bar(int iter, int tid){
    __syncthreads();
    if (tid == 0){
        __threadfence();
        unsigned old = atomicAdd(&g_cnt, 1u);
        if (old == (unsigned)NB*(iter+1) - 1u){
            atomicExch(&g_phase, (unsigned)(iter+1));
        } else {
            while (atomicAdd(&g_phase, 0u) < (unsigned)(iter+1)) { }
        }
        __threadfence();
    }
    __syncthreads();
}

__device__ __forceinline__ void load_atile(char* buf, const __half* Asrc, int k0, int tid){
#pragma unroll
    for (int j = 0; j < 2; j++){
        int c = tid + j*256;           // 512 chunks: 64 rows x 8 x 16B
        int row = c >> 3, cc = c & 7;
        cp16(buf + row*(AROW*2) + cc*16, Asrc + (size_t)row*1024 + k0 + cc*8);
    }
}

__global__ void __launch_bounds__(256,1) lstm_persist(float* __restrict__ out){
    extern __shared__ char smem[];
    __half* Wsm = (__half*)smem;
    char*   Abase = smem + WBYTES;
    float*  stg = (float*)(smem + WBYTES);   // epilogue staging (reuses A bufs)

    const int tid = threadIdx.x;
    const int bid = blockIdx.x;
    const int stage = bid / 43;
    const int q = bid - stage*43;
    const int rows = (q == 42) ? 64 : 96;
    const int row0 = q * 96;
    const int ntn = (rows == 96) ? 3 : 2;    // n-tiles per n-warp
    const int nr = ntn * 16;                  // rows per chunk (48 or 32)
    const int SLD = nr + 4;                   // staging ld (52 or 36), mult of 4
    const int warp = tid >> 5;
    const int wm = warp & 3, wn = warp >> 2;  // 4 m-warps x 2 n-warps

    // ---- load weight slice into smem (once) ----
    {
        const char* Wg = (const char*)(g_Wcat + ((size_t)stage*G4 + row0)*1024);
        for (int c = tid; c < rows*128; c += 256){
            int r = c >> 7, cc = c & 127;
            cp16((char*)Wsm + r*(WPITCH*2) + cc*16, Wg + (size_t)r*2048 + cc*16);
        }
        asm volatile("cp.async.commit_group;\n");
        asm volatile("cp.async.wait_group 0;\n");
        __syncthreads();
    }

    for (int iter = 0; iter < NITER; iter++){
        int t = iter - stage;
        if (t >= 0 && t < TT){
            const __half* Asrc;
            if (stage == 0)      Asrc = (t == 0) ? g_H0h[0] : g_h1p[(t-1)&1];
            else if (stage == 1) Asrc = g_h1p[t&1];
            else                 Asrc = (t == 0) ? g_H0h[1] : g_h2p[(t-1)&1];

            wmma::fragment<wmma::accumulator,16,16,16,float> acc[3];
#pragma unroll
            for (int j = 0; j < 3; j++) wmma::fill_fragment(acc[j], 0.f);

            // prologue: A tiles 0,1
            load_atile(Abase + 0*(64*AROW*2), Asrc, 0, tid);
            asm volatile("cp.async.commit_group;\n");
            load_atile(Abase + 1*(64*AROW*2), Asrc, KT2, tid);
            asm volatile("cp.async.commit_group;\n");

            for (int kc = 0; kc < 16; kc++){
                asm volatile("cp.async.wait_group 1;\n");
                __syncthreads();
                if (kc + 2 < 16)
                    load_atile(Abase + ((kc+2)%3)*(64*AROW*2), Asrc, (kc+2)*KT2, tid);
                asm volatile("cp.async.commit_group;\n");

                const __half* As = (const __half*)(Abase + (kc%3)*(64*AROW*2));
#pragma unroll
                for (int ks = 0; ks < 4; ks++){
                    wmma::fragment<wmma::matrix_a,16,16,16,__half,wmma::row_major> a;
                    wmma::load_matrix_sync(a, As + (wm*16)*AROW + ks*16, AROW);
#pragma unroll
                    for (int j = 0; j < 3; j++){
                        if (j < ntn){
                            wmma::fragment<wmma::matrix_b,16,16,16,__half,wmma::col_major> bf;
                            wmma::load_matrix_sync(bf,
                                Wsm + (size_t)(wn*nr + j*16)*WPITCH + kc*KT2 + ks*16, WPITCH);
                            wmma::mma_sync(acc[j], a, bf, acc[j]);
                        }
                    }
                }
            }
            asm volatile("cp.async.wait_group 0;\n");
            __syncthreads();

            // ---- epilogue in two chunks (wn==ch stores its accs) ----
#pragma unroll
            for (int ch = 0; ch < 2; ch++){
                if (wn == ch){
#pragma unroll
                    for (int j = 0; j < 3; j++)
                        if (j < ntn)
                            wmma::store_matrix_sync(stg + (wm*16)*SLD + j*16, acc[j],
                                                    SLD, wmma::mem_row_major);
                }
                __syncthreads();

                if (stage == 1){
                    float* dst = g_gx2p[t&1];
                    for (int i = tid; i < 64*nr; i += 256){
                        int m = i / nr, r2 = i - m*nr;
                        int grow = row0 + ch*nr + r2;
                        dst[(size_t)m*G4 + grow] = stg[m*SLD + r2] + g_b2[grow];
                    }
                } else {
                    int upc = nr >> 2;
                    int ub = (row0 >> 2) + ch*upc;
                    for (int i = tid; i < 64*upc; i += 256){
                        int m = i & 63, u = i >> 6;
                        float4 gq = *(float4*)&stg[m*SLD + 4*u];
                        int unit = ub + u;
                        int cidx = m*HH + unit;
                        if (stage == 0){
                            float4 gx = *(const float4*)&g_GX1[(((size_t)t*BB)+m)*G4 + row0 + ch*nr + 4*u];
                            float gi = gq.x + gx.x, gf = gq.y + gx.y;
                            float gg = gq.z + gx.z, go = gq.w + gx.w;
                            float c = sigmoidf_(gf)*g_C1[cidx] + sigmoidf_(gi)*tanhf(gg);
                            g_C1[cidx] = c;
                            float hv = sigmoidf_(go)*tanhf(c);
                            g_h1p[t&1][cidx] = __float2half(hv);
                            if (t == TT-1){
                                out[OUT_SEQ + cidx] = hv;
                                out[OUT_SEQ + 2*BH + cidx] = c;
                            }
                        } else {
                            float4 gx = *(const float4*)&g_gx2p[t&1][(size_t)m*G4 + row0 + ch*nr + 4*u];
                            float gi = gq.x + gx.x, gf = gq.y + gx.y;
                            float gg = gq.z + gx.z, go = gq.w + gx.w;
                            float c = sigmoidf_(gf)*g_C2[cidx] + sigmoidf_(gi)*tanhf(gg);
                            g_C2[cidx] = c;
                            float hv = sigmoidf_(go)*tanhf(c);
                            g_h2p[t&1][cidx] = __float2half(hv);
                            out[(size_t)t*BH + cidx] = hv;
                            if (t == TT-1){
                                out[OUT_SEQ + BH + cidx] = hv;
                                out[OUT_SEQ + 3*BH + cidx] = c;
                            }
                        }
                    }
                }
                __syncthreads();
            }
        }
        grid_bar(iter, tid);
    }
}

// ================= launcher =================
extern "C" void kernel_launch(void* const* d_in, const int* in_sizes, int n_in,
                              void* d_out, int out_size){
    const float* x   = (const float*)d_in[0];
    const float* Wih = (const float*)d_in[1];
    const float* Whh = (const float*)d_in[2];
    const float* b   = (const float*)d_in[3];
    const float* h0  = (const float*)d_in[4];
    const float* c0  = (const float*)d_in[5];
    float* out = (float*)d_out;

    cudaFuncSetAttribute(gx_kernel,    cudaFuncAttributeMaxDynamicSharedMemorySize, GX_SMEM);
    cudaFuncSetAttribute(lstm_persist, cudaFuncAttributeMaxDynamicSharedMemorySize, PSMEM);

    prep_w<<<(G4*1024 + 255)/256, 256>>>(Wih, Whh, b);
    prep_x<<<((TT*BB*1024/4) + 255)/256, 256>>>(x);
    init_c<<<64, 1024>>>(h0, c0);
    gx_kernel<<<dim3(64, 512), 256, GX_SMEM>>>();
    lstm_persist<<<NB, 256, PSMEM>>>(out);
}

// round 5
// speedup vs baseline: 1.0731x; 1.0731x over previous
#include <cuda_runtime.h>
#include <cuda_fp16.h>
#include <mma.h>
using namespace nvcuda;

#define TT 512
#define BB 64
#define HH 1024
#define G4 4096
#define BH (BB*HH)
#define OUT_SEQ ((size_t)TT*BB*HH)

// ---- gx (input-projection) GEMM params ----
#define KT2 64
#define NS2 4
#define AROW 72
#define STAGE_BYTES (2*64*AROW*2)
#define GX_SMEM (NS2*STAGE_BYTES)

// ---- persistent kernel params ----
#define NB 129                      // 43 blocks per stage x 3 stages
#define WPITCH 1032                 // halves; row pitch 2064B -> conflict-free ldsm
#define WBYTES (96*WPITCH*2)        // 198144
#define ABYTES (3*64*AROW*2)        // A-tile triple buffer: 27648
#define PSMEM (WBYTES+ABYTES)       // 225792 <= 227KB

// ---------------- device scratch ----------------
__device__ __half g_Wc1h[(size_t)G4*1024];
__device__ __half g_Wcat[(size_t)3*G4*1024];   // [Whh1 | Wih2 | Whh2] permuted
__device__ float  g_b1[G4], g_b2[G4];
__device__ __half g_Xh[(size_t)TT*BB*1024];
__device__ float  g_GX1[(size_t)TT*BB*G4];
__device__ __half g_h1p[2][BH];
__device__ __half g_h2p[2][BH];
__device__ __half g_H0h[2][BH];
__device__ float  g_gx2p[2][(size_t)BB*G4];
__device__ float  g_C1[BH], g_C2[BH];
__device__ unsigned g_cnt0[TT], g_cnt1[TT], g_cnt2[TT];

__device__ __forceinline__ float sigmoidf_(float x){ return 1.f/(1.f+expf(-x)); }

__device__ __forceinline__ void cp16(void* dst, const void* src){
    unsigned s = (unsigned)__cvta_generic_to_shared(dst);
    asm volatile("cp.async.ca.shared.global [%0], [%1], 16;\n" :: "r"(s), "l"(src));
}
__device__ __forceinline__ void cp16cg(void* dst, const void* src){
    unsigned s = (unsigned)__cvta_generic_to_shared(dst);
    asm volatile("cp.async.cg.shared.global [%0], [%1], 16;\n" :: "r"(s), "l"(src));
}
__device__ __forceinline__ void waitc(const unsigned* p, unsigned tgt){
    unsigned v;
    do {
        asm volatile("ld.acquire.gpu.global.u32 %0, [%1];" : "=r"(v) : "l"(p) : "memory");
    } while (v < tgt);
}
__device__ __forceinline__ void arrive(unsigned* p){
    asm volatile("red.release.gpu.global.add.u32 [%0], 1;" :: "l"(p) : "memory");
}

// ================= prep kernels =================
__global__ void prep_w(const float* __restrict__ Wih, const float* __restrict__ Whh,
                       const float* __restrict__ b){
    size_t i = (size_t)blockIdx.x*blockDim.x + threadIdx.x;
    if (i >= (size_t)G4*1024) return;
    int r = (int)(i >> 10), k = (int)(i & 1023);
    int u = r >> 2, g = r & 3;
    int src = (g << 10) | u;
    const size_t L1 = (size_t)G4*1024;
    g_Wc1h[(size_t)r*1024+k]        = __float2half(Wih[(size_t)src*1024+k]);
    g_Wcat[(size_t)r*1024+k]        = __float2half(Whh[(size_t)src*1024+k]);
    g_Wcat[(size_t)(G4+r)*1024+k]   = __float2half(Wih[L1+(size_t)src*1024+k]);
    g_Wcat[(size_t)(2*G4+r)*1024+k] = __float2half(Whh[L1+(size_t)src*1024+k]);
    if (k == 0){ g_b1[r] = b[src]; g_b2[r] = b[G4+src]; }
}

__global__ void prep_x(const float* __restrict__ x){
    size_t i = (size_t)blockIdx.x*blockDim.x + threadIdx.x;
    size_t n4 = (size_t)TT*BB*1024/4;
    if (i >= n4) return;
    float4 v = ((const float4*)x)[i];
    __half2* dst = (__half2*)g_Xh;
    dst[2*i]   = __floats2half2_rn(v.x, v.y);
    dst[2*i+1] = __floats2half2_rn(v.z, v.w);
}

__global__ void init_c(const float* __restrict__ h0, const float* __restrict__ c0){
    int i = blockIdx.x*blockDim.x + threadIdx.x;
    if (i < BH){
        g_C1[i] = c0[i];
        g_C2[i] = c0[BH+i];
        g_H0h[0][i] = __float2half(h0[i]);
        g_H0h[1][i] = __float2half(h0[BH+i]);
    }
    if (i < TT){ g_cnt0[i] = 0; g_cnt1[i] = 0; g_cnt2[i] = 0; }
}

// ================= gx GEMM =================
__device__ __forceinline__ void load_stage2(char* st, const __half* A, int lda,
        const __half* W, int ldw, int k0, int tid)
{
#pragma unroll
    for (int j = 0; j < 4; j++){
        int c = tid + j*256;
        int row = (c & 511) >> 3;
        int cc  = c & 7;
        if (c < 512)
            cp16(st + row*(AROW*2) + cc*16, A + (size_t)row*lda + k0 + cc*8);
        else
            cp16(st + 64*AROW*2 + row*(AROW*2) + cc*16, W + (size_t)row*ldw + k0 + cc*8);
    }
}

__global__ void gx_kernel(){
    extern __shared__ char smem[];
    int n0   = blockIdx.x * 64;
    int row0 = blockIdx.y * 64;
    int tid = threadIdx.x;
    int warp = tid >> 5;
    int wm = warp >> 1, wn = warp & 1;
    const __half* A = g_Xh + (size_t)row0*1024;
    const __half* W = g_Wc1h + (size_t)n0*1024;

    wmma::fragment<wmma::accumulator,16,16,16,float> acc[2];
    wmma::fill_fragment(acc[0], 0.f);
    wmma::fill_fragment(acc[1], 0.f);

#pragma unroll
    for (int p = 0; p < NS2-1; p++){
        load_stage2(smem + p*STAGE_BYTES, A, 1024, W, 1024, p*KT2, tid);
        asm volatile("cp.async.commit_group;\n");
    }
    for (int t = 0; t < 1024/KT2; t++){
        asm volatile("cp.async.wait_group 2;\n");
        __syncthreads();
        int pf = t + NS2 - 1;
        if (pf < 1024/KT2)
            load_stage2(smem + (pf & (NS2-1))*STAGE_BYTES, A, 1024, W, 1024, pf*KT2, tid);
        asm volatile("cp.async.commit_group;\n");

        const __half* As = (const __half*)(smem + (t & (NS2-1))*STAGE_BYTES);
        const __half* Ws = As + 64*AROW;
#pragma unroll
        for (int ks = 0; ks < KT2/16; ks++){
            wmma::fragment<wmma::matrix_a,16,16,16,__half,wmma::row_major> a;
            wmma::fragment<wmma::matrix_b,16,16,16,__half,wmma::col_major> b;
            wmma::load_matrix_sync(a, As + (wm*16)*AROW + ks*16, AROW);
            wmma::load_matrix_sync(b, Ws + (wn*32)*AROW + ks*16, AROW);
            wmma::mma_sync(acc[0], a, b, acc[0]);
            wmma::load_matrix_sync(b, Ws + (wn*32+16)*AROW + ks*16, AROW);
            wmma::mma_sync(acc[1], a, b, acc[1]);
        }
    }
    asm volatile("cp.async.wait_group 0;\n");
    __syncthreads();
    float* sm = (float*)smem;
    wmma::store_matrix_sync(sm + (wm*16)*64 + wn*32,      acc[0], 64, wmma::mem_row_major);
    wmma::store_matrix_sync(sm + (wm*16)*64 + wn*32 + 16, acc[1], 64, wmma::mem_row_major);
    __syncthreads();
#pragma unroll
    for (int i = 0; i < 16; i++){
        int e = tid + i*256;
        int row = e >> 6, col = e & 63;
        g_GX1[((size_t)row0 + row)*G4 + n0 + col] = sm[row*64+col] + g_b1[n0+col];
    }
}

// ================= persistent LSTM kernel =================
__device__ __forceinline__ void load_atile(char* buf, const __half* Asrc, int k0, int tid){
#pragma unroll
    for (int j = 0; j < 2; j++){
        int c = tid + j*256;
        int row = c >> 3, cc = c & 7;
        cp16cg(buf + row*(AROW*2) + cc*16, Asrc + (size_t)row*1024 + k0 + cc*8);
    }
}

__global__ void __launch_bounds__(256,1) lstm_persist(float* __restrict__ out){
    extern __shared__ char smem[];
    __half* Wsm = (__half*)smem;
    char*   Abase = smem + WBYTES;
    float*  stg = (float*)(smem + WBYTES);

    const int tid = threadIdx.x;
    const int bid = blockIdx.x;
    const int stage = bid / 43;
    const int q = bid - stage*43;
    const int rows = (q == 42) ? 64 : 96;
    const int row0 = q * 96;
    const int ntn = (rows == 96) ? 3 : 2;
    const int nr = ntn * 16;
    const int SLD = nr + 4;
    const int warp = tid >> 5;
    const int wm = warp & 3, wn = warp >> 2;

    // ---- load weight slice into smem (once) ----
    {
        const char* Wg = (const char*)(g_Wcat + ((size_t)stage*G4 + row0)*1024);
        for (int c = tid; c < rows*128; c += 256){
            int r = c >> 7, cc = c & 127;
            cp16((char*)Wsm + r*(WPITCH*2) + cc*16, Wg + (size_t)r*2048 + cc*16);
        }
        asm volatile("cp.async.commit_group;\n");
        asm volatile("cp.async.wait_group 0;\n");
        __syncthreads();
    }

    for (int t = 0; t < TT; t++){
        // ---- GEMM gate: wait for this stage's A-matrix ----
        if (tid == 0){
            if (stage == 0){ if (t >= 1) waitc(&g_cnt0[t-1], 43u); }
            else if (stage == 1){ waitc(&g_cnt0[t], 43u); }
            else { if (t >= 1) waitc(&g_cnt2[t-1], 43u); }
        }
        __syncthreads();

        const __half* Asrc;
        if (stage == 0)      Asrc = (t == 0) ? g_H0h[0] : g_h1p[(t-1)&1];
        else if (stage == 1) Asrc = g_h1p[t&1];
        else                 Asrc = (t == 0) ? g_H0h[1] : g_h2p[(t-1)&1];

        wmma::fragment<wmma::accumulator,16,16,16,float> acc[3];
#pragma unroll
        for (int j = 0; j < 3; j++) wmma::fill_fragment(acc[j], 0.f);

        load_atile(Abase + 0*(64*AROW*2), Asrc, 0, tid);
        asm volatile("cp.async.commit_group;\n");
        load_atile(Abase + 1*(64*AROW*2), Asrc, KT2, tid);
        asm volatile("cp.async.commit_group;\n");

        for (int kc = 0; kc < 16; kc++){
            asm volatile("cp.async.wait_group 1;\n");
            __syncthreads();
            if (kc + 2 < 16)
                load_atile(Abase + ((kc+2)%3)*(64*AROW*2), Asrc, (kc+2)*KT2, tid);
            asm volatile("cp.async.commit_group;\n");

            const __half* As = (const __half*)(Abase + (kc%3)*(64*AROW*2));
#pragma unroll
            for (int ks = 0; ks < 4; ks++){
                wmma::fragment<wmma::matrix_a,16,16,16,__half,wmma::row_major> a;
                wmma::load_matrix_sync(a, As + (wm*16)*AROW + ks*16, AROW);
#pragma unroll
                for (int j = 0; j < 3; j++){
                    if (j < ntn){
                        wmma::fragment<wmma::matrix_b,16,16,16,__half,wmma::col_major> bf;
                        wmma::load_matrix_sync(bf,
                            Wsm + (size_t)(wn*nr + j*16)*WPITCH + kc*KT2 + ks*16, WPITCH);
                        wmma::mma_sync(acc[j], a, bf, acc[j]);
                    }
                }
            }
        }
        asm volatile("cp.async.wait_group 0;\n");
        __syncthreads();

        // ---- epilogue gate: buffer-reuse / gx2 availability ----
        if (tid == 0){
            if (stage == 0){ if (t >= 2) waitc(&g_cnt1[t-2], 43u); }
            else if (stage == 1){ if (t >= 2) waitc(&g_cnt2[t-2], 43u); }
            else { waitc(&g_cnt1[t], 43u); }
        }
        __syncthreads();

        // ---- epilogue in two chunks ----
#pragma unroll
        for (int ch = 0; ch < 2; ch++){
            if (wn == ch){
#pragma unroll
                for (int j = 0; j < 3; j++)
                    if (j < ntn)
                        wmma::store_matrix_sync(stg + (wm*16)*SLD + j*16, acc[j],
                                                SLD, wmma::mem_row_major);
            }
            __syncthreads();

            if (stage == 1){
                float* dst = g_gx2p[t&1];
                for (int i = tid; i < 64*nr; i += 256){
                    int m = i / nr, r2 = i - m*nr;
                    int grow = row0 + ch*nr + r2;
                    dst[(size_t)m*G4 + grow] = stg[m*SLD + r2] + g_b2[grow];
                }
            } else {
                int upc = nr >> 2;
                int ub = (row0 >> 2) + ch*upc;
                for (int i = tid; i < 64*upc; i += 256){
                    int m = i & 63, u = i >> 6;
                    float4 gq = *(float4*)&stg[m*SLD + 4*u];
                    int unit = ub + u;
                    int cidx = m*HH + unit;
                    if (stage == 0){
                        float4 gx = *(const float4*)&g_GX1[(((size_t)t*BB)+m)*G4 + row0 + ch*nr + 4*u];
                        float gi = gq.x + gx.x, gf = gq.y + gx.y;
                        float gg = gq.z + gx.z, go = gq.w + gx.w;
                        float c = sigmoidf_(gf)*g_C1[cidx] + sigmoidf_(gi)*tanhf(gg);
                        g_C1[cidx] = c;
                        float hv = sigmoidf_(go)*tanhf(c);
                        g_h1p[t&1][cidx] = __float2half(hv);
                        if (t == TT-1){
                            out[OUT_SEQ + cidx] = hv;
                            out[OUT_SEQ + 2*BH + cidx] = c;
                        }
                    } else {
                        float4 gx = *(const float4*)&g_gx2p[t&1][(size_t)m*G4 + row0 + ch*nr + 4*u];
                        float gi = gq.x + gx.x, gf = gq.y + gx.y;
                        float gg = gq.z + gx.z, go = gq.w + gx.w;
                        float c = sigmoidf_(gf)*g_C2[cidx] + sigmoidf_(gi)*tanhf(gg);
                        g_C2[cidx] = c;
                        float hv = sigmoidf_(go)*tanhf(c);
                        g_h2p[t&1][cidx] = __float2half(hv);
                        out[(size_t)t*BH + cidx] = hv;
                        if (t == TT-1){
                            out[OUT_SEQ + BH + cidx] = hv;
                            out[OUT_SEQ + 3*BH + cidx] = c;
                        }
                    }
                }
            }
            __syncthreads();
        }

        // ---- arrive ----
        if (tid == 0){
            unsigned* c = (stage == 0) ? &g_cnt0[t] : (stage == 1) ? &g_cnt1[t] : &g_cnt2[t];
            arrive(c);
        }
    }
}

// ================= launcher =================
extern "C" void kernel_launch(void* const* d_in, const int* in_sizes, int n_in,
                              void* d_out, int out_size){
    const float* x   = (const float*)d_in[0];
    const float* Wih = (const float*)d_in[1];
    const float* Whh = (const float*)d_in[2];
    const float* b   = (const float*)d_in[3];
    const float* h0  = (const float*)d_in[4];
    const float* c0  = (const float*)d_in[5];
    float* out = (float*)d_out;

    cudaFuncSetAttribute(gx_kernel,    cudaFuncAttributeMaxDynamicSharedMemorySize, GX_SMEM);
    cudaFuncSetAttribute(lstm_persist, cudaFuncAttributeMaxDynamicSharedMemorySize, PSMEM);

    prep_w<<<(G4*1024 + 255)/256, 256>>>(Wih, Whh, b);
    prep_x<<<((TT*BB*1024/4) + 255)/256, 256>>>(x);
    init_c<<<64, 1024>>>(h0, c0);
    gx_kernel<<<dim3(64, 512), 256, GX_SMEM>>>();
    lstm_persist<<<NB, 256, PSMEM>>>(out);
}